// round 16
// baseline (speedup 1.0000x reference)
#include <cuda_runtime.h>
#include <cuda_fp16.h>
#include <stdint.h>

#define BB 2048
#define SS 128
#define DD 128
#define HH 256
#define GG 1024
#define NCELLS 512
#define NCTAS 64             // each CTA owns 32 batch rows, full N=1024
#define THREADS 512
#define MROWS 32
#define CHUNKA 2048          // A k32 chunk: 32 rows x 64B, SW64

// ---- SMEM layout (dynamic): 224KB ----
#define OFF_W    0u          // 3 stages x 32KB = 98304
#define OFF_X    98304u      // 2 x 8KB x-buffers
#define OFF_H1   114688u     // 8 chunks x 2KB = 16KB
#define OFF_H2   131072u
#define OFF_DIN  147456u
#define OFF_C1   163840u     // 32 rows x 256 f32 = 32KB
#define OFF_C2   196608u
#define SMEM_DYN 229376

// ---- device globals ----
__device__ __align__(128) char g_ximg[(size_t)SS * NCTAS * 8192];       // [t][cta][4x2KB chunks]
__device__ __align__(128) char g_wimg[4][32 * 32768];                    // [ws][kblk*4+nblk][32KB]
__device__ float g_bias[4 * GG];
__device__ float g_decout[(size_t)BB * SS * HH];

// ---- PTX helpers ----
__device__ __forceinline__ uint32_t smem_u32(const void* p) {
    uint32_t a;
    asm("{ .reg .u64 t; cvta.to.shared.u64 t, %1; cvt.u32.u64 %0, t; }" : "=r"(a) : "l"(p));
    return a;
}
#define MBAR_INIT(a, c) asm volatile("mbarrier.init.shared.b64 [%0], %1;" :: "r"(a), "r"(c) : "memory")
#define MBAR_EXPECT(a, n) asm volatile("mbarrier.arrive.expect_tx.shared.b64 _, [%0], %1;" :: "r"(a), "r"(n) : "memory")
#define MBAR_WAIT(a, ph) do { \
    uint32_t _m = (a), _p = (ph), _d; \
    asm volatile("{\n\t.reg .pred p;\n\tmbarrier.try_wait.parity.acquire.cta.shared::cta.b64 p, [%1], %2;\n\tselp.b32 %0,1,0,p;\n\t}" \
        : "=r"(_d) : "r"(_m), "r"(_p) : "memory"); \
    if (!_d) { \
        asm volatile("{\n\t.reg .pred P1;\n\tWL_%=:\n\tmbarrier.try_wait.parity.acquire.cta.shared::cta.b64 P1, [%0], %1, 0x989680;\n\t@P1 bra.uni WD_%=;\n\tbra.uni WL_%=;\n\tWD_%=:\n\t}" \
            :: "r"(_m), "r"(_p) : "memory"); \
    } \
} while (0)
#define BULK_LD(sm, g, n, mb) \
    asm volatile("cp.async.bulk.shared::cta.global.mbarrier::complete_tx::bytes [%0], [%1], %2, [%3];" \
        :: "r"(sm), "l"(g), "r"(n), "r"(mb) : "memory")
#define LDSM4(r0, r1, r2, r3, a) \
    asm volatile("ldmatrix.sync.aligned.m8n8.x4.shared.b16 {%0,%1,%2,%3}, [%4];" \
        : "=r"(r0), "=r"(r1), "=r"(r2), "=r"(r3) : "r"(a))
#define MMA16816(d, a, b0, b1) \
    asm volatile("mma.sync.aligned.m16n8k16.row.col.f32.f16.f16.f32 " \
        "{%0,%1,%2,%3},{%4,%5,%6,%7},{%8,%9},{%0,%1,%2,%3};" \
        : "+f"((d)[0]), "+f"((d)[1]), "+f"((d)[2]), "+f"((d)[3]) \
        : "r"((a)[0]), "r"((a)[1]), "r"((a)[2]), "r"((a)[3]), "r"(b0), "r"(b1))

__device__ __forceinline__ float sigf(float x) { return __fdividef(1.f, 1.f + __expf(-x)); }
__device__ __forceinline__ float tanhv(float x) { return 2.f * sigf(2.f * x) - 1.f; }

// ---------------- launch 1: x -> [t][cta64][4 chunks x (32 rows x 64B SW64)] ----
__global__ void conv_x(const float* __restrict__ x) {
    int idx = blockIdx.x * 256 + threadIdx.x;
    if (idx >= BB * SS * 16) return;
    int ud = idx & 15, bt = idx >> 4;
    int t = bt & (SS - 1), b = bt >> 7;
    int d0 = ud * 8;
    const float4* src = (const float4*)(x + ((size_t)b * SS + t) * DD + d0);
    float4 v0 = src[0], v1 = src[1];
    union { uint4 u; __half h[8]; } pk;
    pk.h[0] = __float2half_rn(v0.x); pk.h[1] = __float2half_rn(v0.y);
    pk.h[2] = __float2half_rn(v0.z); pk.h[3] = __float2half_rn(v0.w);
    pk.h[4] = __float2half_rn(v1.x); pk.h[5] = __float2half_rn(v1.y);
    pk.h[6] = __float2half_rn(v1.z); pk.h[7] = __float2half_rn(v1.w);
    int cta = b >> 5, row = b & 31, chunk = d0 >> 5;
    uint32_t colb = (uint32_t)(d0 & 31) * 2;
    char* dst = g_ximg + ((size_t)t * NCTAS + cta) * 8192 + (size_t)chunk * CHUNKA
              + (uint32_t)row * 64 + (colb ^ (((uint32_t)row & 6) << 3));
    *(uint4*)dst = pk.u;
}

// ---------------- launch 2: W -> [ws][kblk*4+nblk] blocks (256 n-rows x 128B, SW128) ----
__global__ void setup_w(const float* wx0, const float* wh0, const float* wx1, const float* wh1,
                        const float* wx2, const float* wh2, const float* wx3, const float* wh3) {
    const int ws = blockIdx.y;
    int idx = blockIdx.x * 256 + threadIdx.x;
    if (idx >= 65536) return;
    int u8 = idx & 7, r = (idx >> 3) & 255, nblk = (idx >> 11) & 3, kblk = idx >> 13;
    const int K1 = (ws == 0) ? DD : HH;
    const int KB = (ws == 0) ? 6 : 8;
    if (kblk >= KB) return;
    const float* wxs[4] = {wx0, wx1, wx2, wx3};
    const float* whs[4] = {wh0, wh1, wh2, wh3};
    int k0 = kblk * 64 + u8 * 8;
    const float* src; int K, k;
    if (k0 < K1) { src = wxs[ws]; K = K1; k = k0; }
    else         { src = whs[ws]; K = HH; k = k0 - K1; }
    int nglob = nblk * 256 + r;
    int u = nglob >> 2, g = nglob & 3;
    const float4* s4 = (const float4*)(src + ((size_t)g * HH + u) * K + k);
    float4 v0 = s4[0], v1 = s4[1];
    union { uint4 u4; __half h[8]; } pk;
    pk.h[0] = __float2half_rn(v0.x); pk.h[1] = __float2half_rn(v0.y);
    pk.h[2] = __float2half_rn(v0.z); pk.h[3] = __float2half_rn(v0.w);
    pk.h[4] = __float2half_rn(v1.x); pk.h[5] = __float2half_rn(v1.y);
    pk.h[6] = __float2half_rn(v1.z); pk.h[7] = __float2half_rn(v1.w);
    char* dst = g_wimg[ws] + (size_t)(kblk * 4 + nblk) * 32768
              + (uint32_t)r * 128 + (((uint32_t)u8 * 16) ^ (((uint32_t)r & 7) << 4));
    *(uint4*)dst = pk.u4;
}

// ---------------- launch 3: bias ----------------
__global__ void setup_bias(const float* b0a, const float* b0b, const float* b1a, const float* b1b,
                           const float* b2a, const float* b2b, const float* b3a, const float* b3b) {
    int idx = blockIdx.x * 256 + threadIdx.x;
    if (idx >= 4 * GG) return;
    int ws = idx >> 10, r = idx & (GG - 1);
    const float* ba[4] = {b0a, b1a, b2a, b3a};
    const float* bb[4] = {b0b, b1b, b2b, b3b};
    int n = r >> 2, g = r & 3;
    g_bias[idx] = ba[ws][g * HH + n] + bb[ws][g * HH + n];
}

// ---------------- launch 4: CTA-autonomous persistent LSTM (32 rows/CTA) ----
// 16 warps; each warp owns a 16-col slice of every 256-col block, both m16 tiles.
__global__ __launch_bounds__(THREADS, 1) void lstm_persist() {
    extern __shared__ __align__(128) char sm[];
    const uint32_t smu = smem_u32(sm);
    __shared__ __align__(8) uint64_t mbW[3];
    __shared__ __align__(8) uint64_t mbX[2];

    const int tid = threadIdx.x;
    const int wl = tid & 31, wid = tid >> 5;   // wid 0..15
    const int cta = blockIdx.x;

    if (tid == 0) {
        for (int i = 0; i < 3; i++) MBAR_INIT(smem_u32(&mbW[i]), 1);
        for (int i = 0; i < 2; i++) MBAR_INIT(smem_u32(&mbX[i]), 1);
    }
    __syncthreads();

    // zero h1,h2,c1,c2
    {
        uint4 z = {0, 0, 0, 0};
        uint4* h1p = (uint4*)(sm + OFF_H1);
        uint4* h2p = (uint4*)(sm + OFF_H2);
        for (int i = tid; i < 1024; i += THREADS) { h1p[i] = z; h2p[i] = z; }
        float* c1p = (float*)(sm + OFF_C1);
        float* c2p = (float*)(sm + OFF_C2);
        for (int i = tid; i < 8192; i += THREADS) { c1p[i] = 0.f; c2p[i] = 0.f; }
    }
    __syncthreads();

    // issue head
    int ihcell = 0, ihst = 0;
#pragma unroll
    for (int i = 0; i < 3; i++) {
        if (tid == 0) {
            uint32_t mb = smem_u32(&mbW[i]);
            MBAR_EXPECT(mb, 32768);
            BULK_LD(smu + OFF_W + (uint32_t)i * 32768u,
                    g_wimg[0] + (size_t)ihst * 32768, 32768, mb);
        }
        ihst++;
    }
    if (tid == 0) {
        uint32_t mb = smem_u32(&mbX[0]);
        MBAR_EXPECT(mb, 8192);
        BULK_LD(smu + OFF_X, g_ximg + (size_t)cta * 8192, 8192, mb);
    }
    __syncthreads();

    int ccb = 0, ccph = 0;

    // frag addressing
    const uint32_t aColBase = (uint32_t)(wl >> 4) * 16;
    const uint32_t aRowL = (uint32_t)(wl & 15);
    const uint32_t aMask = (aRowL & 6) << 3;
    uint32_t aRowOff[2];
    aRowOff[0] = aRowL * 64;
    aRowOff[1] = (aRowL + 16) * 64;
    const uint32_t wr = (uint32_t)(wid * 16 + (wl >> 4) * 8 + (wl & 7));
    const uint32_t wRow = wr * 128;
    const uint32_t wMask = (wr & 7) << 4;
    const uint32_t wCol = (uint32_t)((wl >> 3) & 1) * 16;

    for (int s = 0; s < NCELLS; s++) {
        int ws, KB, nA1c, t, tdec = -1, csel;
        uint32_t a1o, a2o, hO;
        bool xw = false;
        if (s < 2 * SS) {
            t = s >> 1;
            if (!(s & 1)) { ws = 0; KB = 6; nA1c = 4; a1o = OFF_X + (uint32_t)(t & 1) * 8192u;
                            a2o = OFF_H1; csel = 0; hO = OFF_H1; xw = true; }
            else          { ws = 1; KB = 8; nA1c = 8; a1o = OFF_H1; a2o = OFF_H2;
                            csel = 1; hO = OFF_H2; }
        } else {
            t = (s - 2 * SS) >> 1;
            if (!(s & 1)) { ws = 2; KB = 8; nA1c = 8; a1o = (t == 0) ? OFF_DIN : OFF_H2;
                            a2o = OFF_H1; csel = 0; hO = OFF_H1; }
            else          { ws = 3; KB = 8; nA1c = 8; a1o = OFF_H1; a2o = OFF_H2;
                            csel = 1; hO = OFF_H2; tdec = t; }
        }
        if (xw) MBAR_WAIT(smem_u32(&mbX[t & 1]), (t >> 1) & 1);

        float acc[2][4][2][4];   // [mt][nb][f][r]
#pragma unroll
        for (int mt = 0; mt < 2; mt++)
#pragma unroll
            for (int nb = 0; nb < 4; nb++)
#pragma unroll
                for (int f = 0; f < 2; f++)
#pragma unroll
                    for (int r = 0; r < 4; r++) acc[mt][nb][f][r] = 0.f;

        for (int kb = 0; kb < KB; kb++) {
            uint32_t aF[2][4][4];
#pragma unroll
            for (int k16 = 0; k16 < 4; k16++) {
                int chunk = kb * 2 + (k16 >> 1);
                uint32_t cb = (chunk < nA1c) ? a1o + (uint32_t)chunk * CHUNKA
                                             : a2o + (uint32_t)(chunk - nA1c) * CHUNKA;
                uint32_t coff = (aColBase + (uint32_t)(k16 & 1) * 32) ^ aMask;
#pragma unroll
                for (int mt = 0; mt < 2; mt++) {
                    uint32_t addr = smu + cb + aRowOff[mt] + coff;
                    LDSM4(aF[mt][k16][0], aF[mt][k16][1], aF[mt][k16][2], aF[mt][k16][3], addr);
                }
            }
#pragma unroll
            for (int nb = 0; nb < 4; nb++) {
                MBAR_WAIT(smem_u32(&mbW[ccb]), ccph);
                const uint32_t baseW = smu + OFF_W + (uint32_t)ccb * 32768u;
#pragma unroll
                for (int k16 = 0; k16 < 4; k16++) {
                    uint32_t wf[4];
                    uint32_t addr = baseW + wRow + ((wCol + (uint32_t)k16 * 32) ^ wMask);
                    LDSM4(wf[0], wf[1], wf[2], wf[3], addr);
#pragma unroll
                    for (int mt = 0; mt < 2; mt++) {
                        MMA16816(acc[mt][nb][0], aF[mt][k16], wf[0], wf[1]);
                        MMA16816(acc[mt][nb][1], aF[mt][k16], wf[2], wf[3]);
                    }
                }
                __syncthreads();
                if (ihcell < NCELLS) {
                    if (tid == 0) {
                        int iws = (ihcell < 2 * SS) ? (ihcell & 1) : 2 + (ihcell & 1);
                        uint32_t mb = smem_u32(&mbW[ccb]);
                        MBAR_EXPECT(mb, 32768);
                        BULK_LD(smu + OFF_W + (uint32_t)ccb * 32768u,
                                g_wimg[iws] + (size_t)ihst * 32768, 32768, mb);
                    }
                    ihst++;
                    int ins = (ihcell < 2 * SS) ? ((ihcell & 1) ? 32 : 24) : 32;
                    if (ihst == ins) { ihst = 0; ihcell++; }
                }
                if (ccb == 2) { ccb = 0; ccph ^= 1; } else ccb++;
            }
        }

        if (xw && tid == 0 && t + 1 < SS) {
            uint32_t mb = smem_u32(&mbX[(t + 1) & 1]);
            MBAR_EXPECT(mb, 8192);
            BULK_LD(smu + OFF_X + (uint32_t)((t + 1) & 1) * 8192u,
                    g_ximg + ((size_t)(t + 1) * NCTAS + cta) * 8192, 8192, mb);
        }

        // ---- epilogue: gates; c in SMEM f32, bias via __ldg float4, h -> SMEM ----
        {
            float* cb = (float*)(sm + (csel ? OFF_C2 : OFF_C1));
            const float* pb = g_bias + ws * GG;
            const int q = wl & 3, p = q & 1, g = wl >> 2;
            const int rbase = g + (p ? 8 : 0);
#pragma unroll
            for (int mt = 0; mt < 2; mt++) {
                const int rowl = mt * 16 + rbase;
#pragma unroll
                for (int nb = 0; nb < 4; nb++) {
#pragma unroll
                    for (int f = 0; f < 2; f++) {
                        float c0 = acc[mt][nb][f][0], c1 = acc[mt][nb][f][1];
                        float c2 = acc[mt][nb][f][2], c3 = acc[mt][nb][f][3];
                        float e0 = __shfl_xor_sync(0xffffffffu, c0, 1);
                        float e1 = __shfl_xor_sync(0xffffffffu, c1, 1);
                        float e2 = __shfl_xor_sync(0xffffffffu, c2, 1);
                        float e3 = __shfl_xor_sync(0xffffffffu, c3, 1);
                        const int colg = nb * 256 + wid * 16 + f * 8 + (q >> 1) * 4;
                        float zi, zf, zg, zo;
                        if (!p) { zi = c0; zf = c1; zg = e0; zo = e1; }
                        else    { zi = e2; zf = e3; zg = c2; zo = c3; }
                        const float4 bz = __ldg((const float4*)(pb + colg));
                        zi += bz.x; zf += bz.y; zg += bz.z; zo += bz.w;
                        const int un = colg >> 2;
                        float cold = cb[rowl * 256 + un];
                        float ig = sigf(zi), fg = sigf(zf), og = sigf(zo);
                        float gt = tanhv(zg);
                        float cn = fg * cold + ig * gt;
                        float hn = og * tanhv(cn);
                        cb[rowl * 256 + un] = cn;
                        __half* hp = (__half*)(sm + hO + (uint32_t)(un >> 5) * CHUNKA
                                     + (uint32_t)rowl * 64u
                                     + (((uint32_t)(un & 31) * 2u) ^ (((uint32_t)rowl & 6) << 3)));
                        *hp = __float2half_rn(hn);
                        if (tdec >= 0)
                            g_decout[((size_t)(cta * MROWS + rowl)) * (SS * HH)
                                     + (size_t)tdec * HH + un] = hn;
                    }
                }
            }
        }
        __syncthreads();

        // encoder -> decoder reset
        if (s == 2 * SS - 1) {
            uint4 z = {0, 0, 0, 0};
            uint4* h1p = (uint4*)(sm + OFF_H1);
            uint4* h2p = (uint4*)(sm + OFF_H2);
            uint4* dnp = (uint4*)(sm + OFF_DIN);
            for (int i = tid; i < 1024; i += THREADS) { dnp[i] = h2p[i]; h2p[i] = z; h1p[i] = z; }
            float* c1p = (float*)(sm + OFF_C1);
            float* c2p = (float*)(sm + OFF_C2);
            for (int i = tid; i < 8192; i += THREADS) { c1p[i] = 0.f; c2p[i] = 0.f; }
            __syncthreads();
        }
    }
}

// ---------------- launch 5: output projection ----------------
__global__ __launch_bounds__(256, 1)
void out_proj(const float* __restrict__ W, const float* __restrict__ bout,
              float* __restrict__ out) {
    __shared__ float As[2][16][132];
    __shared__ float Bs[2][16][132];
    const int tid = threadIdx.x;
    const int tx = tid & 15, ty = tid >> 4;
    const int m0 = blockIdx.y * 128;
    const int arow = tid >> 1;
    const int acol = (tid & 1) << 3;
    const int ntiles = HH >> 4;

    const float* a0row = g_decout + (size_t)(m0 + arow) * HH + acol;
    const float* w0row = W + (size_t)arow * HH + acol;

    float acc[8][8];
#pragma unroll
    for (int i = 0; i < 8; i++)
#pragma unroll
        for (int j = 0; j < 8; j++) acc[i][j] = 0.f;
    {
        float4 ra0 = *(const float4*)a0row;
        float4 ra1 = *(const float4*)(a0row + 4);
        float4 rb0 = *(const float4*)w0row;
        float4 rb1 = *(const float4*)(w0row + 4);
        float* sa = &As[0][acol][arow];
        float* sb = &Bs[0][acol][arow];
        sa[0*132]=ra0.x; sa[1*132]=ra0.y; sa[2*132]=ra0.z; sa[3*132]=ra0.w;
        sa[4*132]=ra1.x; sa[5*132]=ra1.y; sa[6*132]=ra1.z; sa[7*132]=ra1.w;
        sb[0*132]=rb0.x; sb[1*132]=rb0.y; sb[2*132]=rb0.z; sb[3*132]=rb0.w;
        sb[4*132]=rb1.x; sb[5*132]=rb1.y; sb[6*132]=rb1.z; sb[7*132]=rb1.w;
    }
    __syncthreads();
    for (int t = 0; t < ntiles; t++) {
        const int cur = t & 1;
        const bool more = (t + 1 < ntiles);
        float4 ra0, ra1, rb0, rb1;
        if (more) {
            const float* ap = a0row + (t + 1) * 16;
            const float* wp = w0row + (t + 1) * 16;
            ra0 = *(const float4*)ap; ra1 = *(const float4*)(ap + 4);
            rb0 = *(const float4*)wp; rb1 = *(const float4*)(wp + 4);
        }
#pragma unroll
        for (int k = 0; k < 16; k++) {
            const float* as = &As[cur][k][0];
            const float* bs = &Bs[cur][k][0];
            float4 a0 = *(const float4*)(as + ty * 8);
            float4 a1 = *(const float4*)(as + ty * 8 + 4);
            float4 b0 = *(const float4*)(bs + tx * 8);
            float4 b1 = *(const float4*)(bs + tx * 8 + 4);
            float av[8] = {a0.x, a0.y, a0.z, a0.w, a1.x, a1.y, a1.z, a1.w};
            float bv[8] = {b0.x, b0.y, b0.z, b0.w, b1.x, b1.y, b1.z, b1.w};
#pragma unroll
            for (int i = 0; i < 8; i++)
#pragma unroll
                for (int j = 0; j < 8; j++) acc[i][j] += av[i] * bv[j];
        }
        if (more) {
            const int nxt = cur ^ 1;
            float* sa = &As[nxt][acol][arow];
            float* sb = &Bs[nxt][acol][arow];
            sa[0*132]=ra0.x; sa[1*132]=ra0.y; sa[2*132]=ra0.z; sa[3*132]=ra0.w;
            sa[4*132]=ra1.x; sa[5*132]=ra1.y; sa[6*132]=ra1.z; sa[7*132]=ra1.w;
            sb[0*132]=rb0.x; sb[1*132]=rb0.y; sb[2*132]=rb0.z; sb[3*132]=rb0.w;
            sb[4*132]=rb1.x; sb[5*132]=rb1.y; sb[6*132]=rb1.z; sb[7*132]=rb1.w;
        }
        __syncthreads();
    }
#pragma unroll
    for (int i = 0; i < 8; i++) {
        const int m = m0 + ty * 8 + i;
#pragma unroll
        for (int j = 0; j < 8; j++) {
            const int col = tx * 8 + j;
            out[(size_t)m * DD + col] = acc[i][j] + bout[col];
        }
    }
}

// ---------------- host ----------------
extern "C" void kernel_launch(void* const* d_in, const int* in_sizes, int n_in,
                              void* d_out, int out_size) {
    (void)in_sizes; (void)n_in; (void)out_size;
    const float* x = (const float*)d_in[0];

    cudaFuncSetAttribute(lstm_persist, cudaFuncAttributeMaxDynamicSharedMemorySize, SMEM_DYN);

    conv_x<<<(BB * SS * 16 + 255) / 256, 256>>>(x);                          // launch 1
    setup_w<<<dim3(256, 4), 256>>>(                                          // launch 2
        (const float*)d_in[1], (const float*)d_in[2],
        (const float*)d_in[5], (const float*)d_in[6],
        (const float*)d_in[9], (const float*)d_in[10],
        (const float*)d_in[13], (const float*)d_in[14]);
    setup_bias<<<(4 * GG + 255) / 256, 256>>>(                               // launch 3
        (const float*)d_in[3], (const float*)d_in[4],
        (const float*)d_in[7], (const float*)d_in[8],
        (const float*)d_in[11], (const float*)d_in[12],
        (const float*)d_in[15], (const float*)d_in[16]);
    lstm_persist<<<NCTAS, THREADS, SMEM_DYN>>>();                            // launch 4 (ncu)
    out_proj<<<dim3(1, (BB * SS) / 128), 256>>>((const float*)d_in[17],      // launch 5
                                                (const float*)d_in[18],
                                                (float*)d_out);
}

// round 17
// speedup vs baseline: 1.9835x; 1.9835x over previous
#include <cuda_runtime.h>
#include <cuda_fp16.h>
#include <stdint.h>

#define BB 2048
#define SS 128
#define DD 128
#define HH 256
#define GG 1024
#define NCELLS 512
#define NCTAS 128            // each CTA owns 16 batch rows, full N=1024
#define THREADS 256
#define NWB 6                // W ring depth

// ---- SMEM layout (dynamic): 224KB ----
#define OFF_W    0u          // 6 stages x 32KB = 196608
#define OFF_X    196608u     // 2 x 4KB x-buffers
#define OFF_H1   204800u     // 8 chunks x 1KB (16 rows x 64B, SW64)
#define OFF_H2   212992u
#define OFF_DIN  221184u
#define SMEM_DYN 229376

// ---- device globals ----
__device__ __align__(128) char g_ximg[(size_t)SS * NCTAS * 4096];       // [t][cta][4x1KB chunks]
__device__ __align__(128) char g_wimg[4][32 * 32768];                    // [ws][kblk*4+nblk][32KB]
__device__ float g_bias[4 * GG];
__device__ float g_decout[(size_t)BB * SS * HH];

// ---- PTX helpers ----
__device__ __forceinline__ uint32_t smem_u32(const void* p) {
    uint32_t a;
    asm("{ .reg .u64 t; cvta.to.shared.u64 t, %1; cvt.u32.u64 %0, t; }" : "=r"(a) : "l"(p));
    return a;
}
#define MBAR_INIT(a, c) asm volatile("mbarrier.init.shared.b64 [%0], %1;" :: "r"(a), "r"(c) : "memory")
#define MBAR_EXPECT(a, n) asm volatile("mbarrier.arrive.expect_tx.shared.b64 _, [%0], %1;" :: "r"(a), "r"(n) : "memory")
#define MBAR_WAIT(a, ph) do { \
    uint32_t _m = (a), _p = (ph), _d; \
    asm volatile("{\n\t.reg .pred p;\n\tmbarrier.try_wait.parity.acquire.cta.shared::cta.b64 p, [%1], %2;\n\tselp.b32 %0,1,0,p;\n\t}" \
        : "=r"(_d) : "r"(_m), "r"(_p) : "memory"); \
    if (!_d) { \
        asm volatile("{\n\t.reg .pred P1;\n\tWL_%=:\n\tmbarrier.try_wait.parity.acquire.cta.shared::cta.b64 P1, [%0], %1, 0x989680;\n\t@P1 bra.uni WD_%=;\n\tbra.uni WL_%=;\n\tWD_%=:\n\t}" \
            :: "r"(_m), "r"(_p) : "memory"); \
    } \
} while (0)
#define BULK_LD(sm, g, n, mb) \
    asm volatile("cp.async.bulk.shared::cta.global.mbarrier::complete_tx::bytes [%0], [%1], %2, [%3];" \
        :: "r"(sm), "l"(g), "r"(n), "r"(mb) : "memory")
#define LDSM4(r0, r1, r2, r3, a) \
    asm volatile("ldmatrix.sync.aligned.m8n8.x4.shared.b16 {%0,%1,%2,%3}, [%4];" \
        : "=r"(r0), "=r"(r1), "=r"(r2), "=r"(r3) : "r"(a))
#define MMA16816(d, a, b0, b1) \
    asm volatile("mma.sync.aligned.m16n8k16.row.col.f32.f16.f16.f32 " \
        "{%0,%1,%2,%3},{%4,%5,%6,%7},{%8,%9},{%0,%1,%2,%3};" \
        : "+f"((d)[0]), "+f"((d)[1]), "+f"((d)[2]), "+f"((d)[3]) \
        : "r"((a)[0]), "r"((a)[1]), "r"((a)[2]), "r"((a)[3]), "r"(b0), "r"(b1))

__device__ __forceinline__ float sigf(float x) { return __fdividef(1.f, 1.f + __expf(-x)); }
__device__ __forceinline__ float tanhv(float x) { return 2.f * sigf(2.f * x) - 1.f; }

// ---------------- launch 1: x -> [t][cta][4 chunks x (16 rows x 64B SW64)] ----
__global__ void conv_x(const float* __restrict__ x) {
    int idx = blockIdx.x * 256 + threadIdx.x;
    if (idx >= BB * SS * 16) return;
    int ud = idx & 15, bt = idx >> 4;
    int t = bt & (SS - 1), b = bt >> 7;
    int d0 = ud * 8;
    const float4* src = (const float4*)(x + ((size_t)b * SS + t) * DD + d0);
    float4 v0 = src[0], v1 = src[1];
    union { uint4 u; __half h[8]; } pk;
    pk.h[0] = __float2half_rn(v0.x); pk.h[1] = __float2half_rn(v0.y);
    pk.h[2] = __float2half_rn(v0.z); pk.h[3] = __float2half_rn(v0.w);
    pk.h[4] = __float2half_rn(v1.x); pk.h[5] = __float2half_rn(v1.y);
    pk.h[6] = __float2half_rn(v1.z); pk.h[7] = __float2half_rn(v1.w);
    int cta = b >> 4, row = b & 15, chunk = d0 >> 5;
    uint32_t colb = (uint32_t)(d0 & 31) * 2;
    char* dst = g_ximg + ((size_t)t * NCTAS + cta) * 4096 + (size_t)chunk * 1024
              + (uint32_t)row * 64 + (colb ^ (((uint32_t)row & 6) << 3));
    *(uint4*)dst = pk.u;
}

// ---------------- launch 2: W -> [ws][kblk*4+nblk] blocks (256 n-rows x 128B, SW128) ----
__global__ void setup_w(const float* wx0, const float* wh0, const float* wx1, const float* wh1,
                        const float* wx2, const float* wh2, const float* wx3, const float* wh3) {
    const int ws = blockIdx.y;
    int idx = blockIdx.x * 256 + threadIdx.x;
    if (idx >= 65536) return;
    int u8 = idx & 7, r = (idx >> 3) & 255, nblk = (idx >> 11) & 3, kblk = idx >> 13;
    const int K1 = (ws == 0) ? DD : HH;
    const int KB = (ws == 0) ? 6 : 8;
    if (kblk >= KB) return;
    const float* wxs[4] = {wx0, wx1, wx2, wx3};
    const float* whs[4] = {wh0, wh1, wh2, wh3};
    int k0 = kblk * 64 + u8 * 8;
    const float* src; int K, k;
    if (k0 < K1) { src = wxs[ws]; K = K1; k = k0; }
    else         { src = whs[ws]; K = HH; k = k0 - K1; }
    int nglob = nblk * 256 + r;
    int u = nglob >> 2, g = nglob & 3;
    const float4* s4 = (const float4*)(src + ((size_t)g * HH + u) * K + k);
    float4 v0 = s4[0], v1 = s4[1];
    union { uint4 u4; __half h[8]; } pk;
    pk.h[0] = __float2half_rn(v0.x); pk.h[1] = __float2half_rn(v0.y);
    pk.h[2] = __float2half_rn(v0.z); pk.h[3] = __float2half_rn(v0.w);
    pk.h[4] = __float2half_rn(v1.x); pk.h[5] = __float2half_rn(v1.y);
    pk.h[6] = __float2half_rn(v1.z); pk.h[7] = __float2half_rn(v1.w);
    char* dst = g_wimg[ws] + (size_t)(kblk * 4 + nblk) * 32768
              + (uint32_t)r * 128 + (((uint32_t)u8 * 16) ^ (((uint32_t)r & 7) << 4));
    *(uint4*)dst = pk.u4;
}

// ---------------- launch 3: bias ----------------
__global__ void setup_bias(const float* b0a, const float* b0b, const float* b1a, const float* b1b,
                           const float* b2a, const float* b2b, const float* b3a, const float* b3b) {
    int idx = blockIdx.x * 256 + threadIdx.x;
    if (idx >= 4 * GG) return;
    int ws = idx >> 10, r = idx & (GG - 1);
    const float* ba[4] = {b0a, b1a, b2a, b3a};
    const float* bb[4] = {b0b, b1b, b2b, b3b};
    int n = r >> 2, g = r & 3;
    g_bias[idx] = ba[ws][g * HH + n] + bb[ws][g * HH + n];
}

// ---------------- launch 4: CTA-autonomous persistent LSTM ----------------
// 6-deep W ring, one __syncthreads per kb, c in registers, bias via __ldg.
__global__ __launch_bounds__(THREADS, 1) void lstm_persist() {
    extern __shared__ __align__(128) char sm[];
    const uint32_t smu = smem_u32(sm);
    __shared__ __align__(8) uint64_t mbW[NWB];
    __shared__ __align__(8) uint64_t mbX[2];

    const int tid = threadIdx.x;
    const int wl = tid & 31, wid = tid >> 5;
    const int cta = blockIdx.x;

    if (tid == 0) {
        for (int i = 0; i < NWB; i++) MBAR_INIT(smem_u32(&mbW[i]), 1);
        for (int i = 0; i < 2; i++) MBAR_INIT(smem_u32(&mbX[i]), 1);
    }
    __syncthreads();

    // zero h1,h2
    {
        uint4 z = {0, 0, 0, 0};
        uint4* h1p = (uint4*)(sm + OFF_H1);
        uint4* h2p = (uint4*)(sm + OFF_H2);
        for (int i = tid; i < 512; i += THREADS) { h1p[i] = z; h2p[i] = z; }
    }
    __syncthreads();

    // c-state registers
    float cR1[16], cR2[16];
#pragma unroll
    for (int i = 0; i < 16; i++) { cR1[i] = 0.f; cR2[i] = 0.f; }

    // ---- W issue state (global slot schedule) ----
    int ihcell = 0, ihst = 0, isb = 0;
    auto issueOne = [&]() {
        if (ihcell >= NCELLS) return;
        if (tid == 0) {
            int iws = (ihcell < 2 * SS) ? (ihcell & 1) : 2 + (ihcell & 1);
            uint32_t mb = smem_u32(&mbW[isb]);
            MBAR_EXPECT(mb, 32768);
            BULK_LD(smu + OFF_W + (uint32_t)isb * 32768u,
                    g_wimg[iws] + (size_t)ihst * 32768, 32768, mb);
        }
        ihst++;
        int ins = (ihcell < 2 * SS) ? ((ihcell & 1) ? 32 : 24) : 32;
        if (ihst == ins) { ihst = 0; ihcell++; }
        isb = (isb == NWB - 1) ? 0 : isb + 1;
    };

    // prime: 6 W slots + x(0)
#pragma unroll
    for (int i = 0; i < NWB; i++) issueOne();
    if (tid == 0) {
        uint32_t mb = smem_u32(&mbX[0]);
        MBAR_EXPECT(mb, 4096);
        BULK_LD(smu + OFF_X, g_ximg + (size_t)cta * 4096, 4096, mb);
    }
    __syncthreads();

    int ccb = 0, ccph = 0;

    // frag addressing
    const uint32_t aColBase = (uint32_t)(wl >> 4) * 16;
    const uint32_t aRow = (uint32_t)(wl & 15);
    uint32_t wRow[2], wMask[2];
#pragma unroll
    for (int j2 = 0; j2 < 2; j2++) {
        uint32_t r = (uint32_t)(wid * 32 + (j2 * 2 + (wl >> 4)) * 8 + (wl & 7));
        wRow[j2] = r * 128; wMask[j2] = (r & 7) << 4;
    }
    const uint32_t wCol = (uint32_t)((wl >> 3) & 1) * 16;

    for (int s = 0; s < NCELLS; s++) {
        int ws, KB, nA1c, t, tdec = -1, csel;
        uint32_t a1o, a2o, hO;
        bool xw = false;
        if (s < 2 * SS) {
            t = s >> 1;
            if (!(s & 1)) { ws = 0; KB = 6; nA1c = 4; a1o = OFF_X + (uint32_t)(t & 1) * 4096u;
                            a2o = OFF_H1; csel = 0; hO = OFF_H1; xw = true; }
            else          { ws = 1; KB = 8; nA1c = 8; a1o = OFF_H1; a2o = OFF_H2;
                            csel = 1; hO = OFF_H2; }
        } else {
            t = (s - 2 * SS) >> 1;
            if (!(s & 1)) { ws = 2; KB = 8; nA1c = 8; a1o = (t == 0) ? OFF_DIN : OFF_H2;
                            a2o = OFF_H1; csel = 0; hO = OFF_H1; }
            else          { ws = 3; KB = 8; nA1c = 8; a1o = OFF_H1; a2o = OFF_H2;
                            csel = 1; hO = OFF_H2; tdec = t; }
        }
        if (xw) MBAR_WAIT(smem_u32(&mbX[t & 1]), (t >> 1) & 1);

        float acc[4][4][4];
#pragma unroll
        for (int nb = 0; nb < 4; nb++)
#pragma unroll
            for (int f = 0; f < 4; f++)
#pragma unroll
                for (int r = 0; r < 4; r++) acc[nb][f][r] = 0.f;

        for (int kb = 0; kb < KB; kb++) {
            uint32_t aF[4][4];
#pragma unroll
            for (int k16 = 0; k16 < 4; k16++) {
                int chunk = kb * 2 + (k16 >> 1);
                uint32_t cb = (chunk < nA1c) ? a1o + (uint32_t)chunk * 1024u
                                             : a2o + (uint32_t)(chunk - nA1c) * 1024u;
                uint32_t addr = smu + cb + aRow * 64
                              + ((aColBase + (uint32_t)(k16 & 1) * 32) ^ ((aRow & 6) << 3));
                LDSM4(aF[k16][0], aF[k16][1], aF[k16][2], aF[k16][3], addr);
            }
#pragma unroll
            for (int nb = 0; nb < 4; nb++) {
                MBAR_WAIT(smem_u32(&mbW[ccb]), ccph);
                const uint32_t baseW = smu + OFF_W + (uint32_t)ccb * 32768u;
#pragma unroll
                for (int k16 = 0; k16 < 4; k16++) {
                    uint32_t wf[8];
#pragma unroll
                    for (int j2 = 0; j2 < 2; j2++) {
                        uint32_t addr = baseW + wRow[j2]
                                      + ((wCol + (uint32_t)k16 * 32) ^ wMask[j2]);
                        LDSM4(wf[4*j2+0], wf[4*j2+1], wf[4*j2+2], wf[4*j2+3], addr);
                    }
                    MMA16816(acc[nb][0], aF[k16], wf[0], wf[1]);
                    MMA16816(acc[nb][1], aF[k16], wf[2], wf[3]);
                    MMA16816(acc[nb][2], aF[k16], wf[4], wf[5]);
                    MMA16816(acc[nb][3], aF[k16], wf[6], wf[7]);
                }
                if (ccb == NWB - 1) { ccb = 0; ccph ^= 1; } else ccb++;
            }
            __syncthreads();               // all warps done with the 4 consumed buffers
            issueOne(); issueOne(); issueOne(); issueOne();
        }

        if (xw && tid == 0 && t + 1 < SS) {
            uint32_t mb = smem_u32(&mbX[(t + 1) & 1]);
            MBAR_EXPECT(mb, 4096);
            BULK_LD(smu + OFF_X + (uint32_t)((t + 1) & 1) * 4096u,
                    g_ximg + ((size_t)(t + 1) * NCTAS + cta) * 4096, 4096, mb);
        }

        // ---- epilogue: gates; c in REGISTERS, bias via __ldg float4, h -> SMEM ----
        {
            const float* pb = g_bias + ws * GG;
            float* cR = csel ? cR2 : cR1;
            const int q = wl & 3, p = q & 1, g = wl >> 2;
            const int rowl = g + (p ? 8 : 0);
#pragma unroll
            for (int nb = 0; nb < 4; nb++) {
#pragma unroll
                for (int f = 0; f < 4; f++) {
                    float c0 = acc[nb][f][0], c1 = acc[nb][f][1];
                    float c2 = acc[nb][f][2], c3 = acc[nb][f][3];
                    float e0 = __shfl_xor_sync(0xffffffffu, c0, 1);
                    float e1 = __shfl_xor_sync(0xffffffffu, c1, 1);
                    float e2 = __shfl_xor_sync(0xffffffffu, c2, 1);
                    float e3 = __shfl_xor_sync(0xffffffffu, c3, 1);
                    const int colg = nb * 256 + wid * 32 + f * 8 + (q >> 1) * 4;
                    float zi, zf, zg, zo;
                    if (!p) { zi = c0; zf = c1; zg = e0; zo = e1; }
                    else    { zi = e2; zf = e3; zg = c2; zo = c3; }
                    const float4 bz = __ldg((const float4*)(pb + colg));
                    zi += bz.x; zf += bz.y; zg += bz.z; zo += bz.w;
                    const int un = colg >> 2;
                    const int ci = nb * 4 + f;
                    float cold = cR[ci];
                    float ig = sigf(zi), fg = sigf(zf), og = sigf(zo);
                    float gt = tanhv(zg);
                    float cn = fg * cold + ig * gt;
                    float hn = og * tanhv(cn);
                    cR[ci] = cn;
                    __half* hp = (__half*)(sm + hO + (uint32_t)(un >> 5) * 1024u
                                 + (uint32_t)rowl * 64u
                                 + (((uint32_t)(un & 31) * 2u) ^ (((uint32_t)rowl & 6) << 3)));
                    *hp = __float2half_rn(hn);
                    if (tdec >= 0)
                        g_decout[((size_t)(cta * 16 + rowl)) * (SS * HH)
                                 + (size_t)tdec * HH + un] = hn;
                }
            }
        }
        __syncthreads();

        // encoder -> decoder reset
        if (s == 2 * SS - 1) {
            uint4 z = {0, 0, 0, 0};
            uint4* h1p = (uint4*)(sm + OFF_H1);
            uint4* h2p = (uint4*)(sm + OFF_H2);
            uint4* dnp = (uint4*)(sm + OFF_DIN);
            for (int i = tid; i < 512; i += THREADS) { dnp[i] = h2p[i]; h2p[i] = z; h1p[i] = z; }
#pragma unroll
            for (int i = 0; i < 16; i++) { cR1[i] = 0.f; cR2[i] = 0.f; }
            __syncthreads();
        }
    }
}

// ---------------- launch 5: output projection ----------------
__global__ __launch_bounds__(256, 1)
void out_proj(const float* __restrict__ W, const float* __restrict__ bout,
              float* __restrict__ out) {
    __shared__ float As[2][16][132];
    __shared__ float Bs[2][16][132];
    const int tid = threadIdx.x;
    const int tx = tid & 15, ty = tid >> 4;
    const int m0 = blockIdx.y * 128;
    const int arow = tid >> 1;
    const int acol = (tid & 1) << 3;
    const int ntiles = HH >> 4;

    const float* a0row = g_decout + (size_t)(m0 + arow) * HH + acol;
    const float* w0row = W + (size_t)arow * HH + acol;

    float acc[8][8];
#pragma unroll
    for (int i = 0; i < 8; i++)
#pragma unroll
        for (int j = 0; j < 8; j++) acc[i][j] = 0.f;
    {
        float4 ra0 = *(const float4*)a0row;
        float4 ra1 = *(const float4*)(a0row + 4);
        float4 rb0 = *(const float4*)w0row;
        float4 rb1 = *(const float4*)(w0row + 4);
        float* sa = &As[0][acol][arow];
        float* sb = &Bs[0][acol][arow];
        sa[0*132]=ra0.x; sa[1*132]=ra0.y; sa[2*132]=ra0.z; sa[3*132]=ra0.w;
        sa[4*132]=ra1.x; sa[5*132]=ra1.y; sa[6*132]=ra1.z; sa[7*132]=ra1.w;
        sb[0*132]=rb0.x; sb[1*132]=rb0.y; sb[2*132]=rb0.z; sb[3*132]=rb0.w;
        sb[4*132]=rb1.x; sb[5*132]=rb1.y; sb[6*132]=rb1.z; sb[7*132]=rb1.w;
    }
    __syncthreads();
    for (int t = 0; t < ntiles; t++) {
        const int cur = t & 1;
        const bool more = (t + 1 < ntiles);
        float4 ra0, ra1, rb0, rb1;
        if (more) {
            const float* ap = a0row + (t + 1) * 16;
            const float* wp = w0row + (t + 1) * 16;
            ra0 = *(const float4*)ap; ra1 = *(const float4*)(ap + 4);
            rb0 = *(const float4*)wp; rb1 = *(const float4*)(wp + 4);
        }
#pragma unroll
        for (int k = 0; k < 16; k++) {
            const float* as = &As[cur][k][0];
            const float* bs = &Bs[cur][k][0];
            float4 a0 = *(const float4*)(as + ty * 8);
            float4 a1 = *(const float4*)(as + ty * 8 + 4);
            float4 b0 = *(const float4*)(bs + tx * 8);
            float4 b1 = *(const float4*)(bs + tx * 8 + 4);
            float av[8] = {a0.x, a0.y, a0.z, a0.w, a1.x, a1.y, a1.z, a1.w};
            float bv[8] = {b0.x, b0.y, b0.z, b0.w, b1.x, b1.y, b1.z, b1.w};
#pragma unroll
            for (int i = 0; i < 8; i++)
#pragma unroll
                for (int j = 0; j < 8; j++) acc[i][j] += av[i] * bv[j];
        }
        if (more) {
            const int nxt = cur ^ 1;
            float* sa = &As[nxt][acol][arow];
            float* sb = &Bs[nxt][acol][arow];
            sa[0*132]=ra0.x; sa[1*132]=ra0.y; sa[2*132]=ra0.z; sa[3*132]=ra0.w;
            sa[4*132]=ra1.x; sa[5*132]=ra1.y; sa[6*132]=ra1.z; sa[7*132]=ra1.w;
            sb[0*132]=rb0.x; sb[1*132]=rb0.y; sb[2*132]=rb0.z; sb[3*132]=rb0.w;
            sb[4*132]=rb1.x; sb[5*132]=rb1.y; sb[6*132]=rb1.z; sb[7*132]=rb1.w;
        }
        __syncthreads();
    }
#pragma unroll
    for (int i = 0; i < 8; i++) {
        const int m = m0 + ty * 8 + i;
#pragma unroll
        for (int j = 0; j < 8; j++) {
            const int col = tx * 8 + j;
            out[(size_t)m * DD + col] = acc[i][j] + bout[col];
        }
    }
}

// ---------------- host ----------------
extern "C" void kernel_launch(void* const* d_in, const int* in_sizes, int n_in,
                              void* d_out, int out_size) {
    (void)in_sizes; (void)n_in; (void)out_size;
    const float* x = (const float*)d_in[0];

    cudaFuncSetAttribute(lstm_persist, cudaFuncAttributeMaxDynamicSharedMemorySize, SMEM_DYN);

    conv_x<<<(BB * SS * 16 + 255) / 256, 256>>>(x);                          // launch 1
    setup_w<<<dim3(256, 4), 256>>>(                                          // launch 2
        (const float*)d_in[1], (const float*)d_in[2],
        (const float*)d_in[5], (const float*)d_in[6],
        (const float*)d_in[9], (const float*)d_in[10],
        (const float*)d_in[13], (const float*)d_in[14]);
    setup_bias<<<(4 * GG + 255) / 256, 256>>>(                               // launch 3
        (const float*)d_in[3], (const float*)d_in[4],
        (const float*)d_in[7], (const float*)d_in[8],
        (const float*)d_in[11], (const float*)d_in[12],
        (const float*)d_in[15], (const float*)d_in[16]);
    lstm_persist<<<NCTAS, THREADS, SMEM_DYN>>>();                            // launch 4 (ncu)
    out_proj<<<dim3(1, (BB * SS) / 128), 256>>>((const float*)d_in[17],      // launch 5
                                                (const float*)d_in[18],
                                                (float*)d_out);
}